// round 12
// baseline (speedup 1.0000x reference)
#include <cuda_runtime.h>

// SSIM loss, fused single pass. (u,v)=(p+t,p-t) rotation, f32x2 packed.
// Software-pipelined window: 1-row-lookahead LDS (taps + Q-ring), no own-regs,
// branch-free mainloop (invalid rows zero-written).
// NT=256, 2 cols/thread, 6 strips -> grid 288 -> 2 CTAs/SM -> 4 warps/SMSP.
// 4 rows per barrier (8 row buffers), 4-row LDG prefetch.
// UV ring in registers (static slots); Q ring in smem. 1 rcp per 2 cols.
// Last-block finalize. pred/target: (16,3,512,512) fp32 -> out: 16 fp32.

#define WIDTH   512
#define HEIGHT  512
#define PADR    5
#define NT      256
#define NSTRIP  6
#define STRIPH  86
#define RS2     528
#define NBLOCKS (48 * NSTRIP)

// smem byte offsets (dynamic)
#define OF_Q    0              // 11*256*16 = 45056
#define OF_ROW  45056          // 8*528*8   = 33792
#define OF_RED  78848          // 256*4
#define SMEM_SZ 79872

// SSIM constants with 1/121 folded out: K1=C1*121^2, K2=C2*121^2
#define K1f 1.4641f
#define K2f 13.1769f

typedef unsigned long long u64;

__device__ float g_partials[NBLOCKS];
__device__ unsigned int g_count;

__device__ __forceinline__ u64 pk2(float a, float b) {
    u64 r; asm("mov.b64 %0,{%1,%2};" : "=l"(r) : "f"(a), "f"(b)); return r;
}
__device__ __forceinline__ float2 up2(u64 a) {
    float2 r; asm("mov.b64 {%0,%1},%2;" : "=f"(r.x), "=f"(r.y) : "l"(a)); return r;
}
__device__ __forceinline__ u64 add2(u64 a, u64 b) {
    u64 r; asm("add.rn.f32x2 %0,%1,%2;" : "=l"(r) : "l"(a), "l"(b)); return r;
}
__device__ __forceinline__ u64 mul2(u64 a, u64 b) {
    u64 r; asm("mul.rn.f32x2 %0,%1,%2;" : "=l"(r) : "l"(a), "l"(b)); return r;
}
__device__ __forceinline__ u64 fma2(u64 a, u64 b, u64 c) {
    u64 r; asm("fma.rn.f32x2 %0,%1,%2,%3;" : "=l"(r) : "l"(a), "l"(b), "l"(c)); return r;
}
__device__ __forceinline__ float rcpa(float x) {
    float r; asm("rcp.approx.f32 %0,%1;" : "=f"(r) : "f"(x)); return r;
}

// Load the 12 window taps (buffer idx [x0+3, x0+14]) for 2 output columns.
// All loads aligned: LDS.64 + 5x LDS.128 + LDS.64.
__device__ __forceinline__ void load_taps(const float2* __restrict__ row, int x0,
                                          u64 T[12])
{
    T[0] = *(const u64*)(row + x0 + 3);
    ulonglong2 A = *(const ulonglong2*)(row + x0 + 4);
    ulonglong2 B = *(const ulonglong2*)(row + x0 + 6);
    ulonglong2 C = *(const ulonglong2*)(row + x0 + 8);
    ulonglong2 D = *(const ulonglong2*)(row + x0 + 10);
    ulonglong2 E = *(const ulonglong2*)(row + x0 + 12);
    T[1] = A.x; T[2] = A.y; T[3] = B.x; T[4] = B.y;
    T[5] = C.x; T[6] = C.y; T[7] = D.x; T[8] = D.y;
    T[9] = E.x; T[10] = E.y;
    T[11] = *(const u64*)(row + x0 + 14);
}

// Tree-structured 11-tap window sums for 2 cols from preloaded taps.
__device__ __forceinline__ void hwin_math(const u64 T[12], u64 hUV[2], u64 hQ[2])
{
    u64 s1 = add2(add2(T[1], T[2]), add2(T[3], T[4]));
    u64 s2 = add2(add2(T[5], T[6]), add2(T[7], T[8]));
    u64 s3 = add2(T[9], T[10]);
    u64 mid = add2(add2(s1, s2), s3);
    hUV[0] = add2(mid, T[0]);
    hUV[1] = add2(mid, T[11]);

    u64 q1 = fma2(T[2], T[2], mul2(T[1], T[1]));
    q1 = fma2(T[3], T[3], q1);
    q1 = fma2(T[4], T[4], q1);
    q1 = fma2(T[5], T[5], q1);
    u64 q2 = fma2(T[7], T[7], mul2(T[6], T[6]));
    q2 = fma2(T[8], T[8], q2);
    q2 = fma2(T[9], T[9], q2);
    q2 = fma2(T[10], T[10], q2);
    u64 midq = add2(q1, q2);
    hQ[0] = fma2(T[0], T[0], midq);
    hQ[1] = fma2(T[11], T[11], midq);
}

// SSIM emit for 2 columns; one rcp serves both divides.
__device__ __forceinline__ void emit2(const u64 SUV[2], const u64 SQ2[2], float& acc)
{
    float n[2], d[2];
#pragma unroll
    for (int c = 0; c < 2; c++) {
        float2 qf = up2(SQ2[c]);                 // (Qu, Qv)
        float2 s2 = up2(mul2(SUV[c], SUV[c]));   // (Su^2, Sv^2)
        float A = s2.x - s2.y;                   // 4*Mx*My
        float B = s2.x + s2.y;                   // 2*(Mx^2+My^2)
        float qd = qf.x - qf.y;                  // 4*S(pt)
        float qs = qf.x + qf.y;                  // 2*(Sp2+St2)
        float a  = fmaf(0.5f, A, K1f);
        float b  = fmaf(60.5f, qd, fmaf(-0.5f, A, K2f));
        n[c] = a * b;
        float d1 = fmaf(0.5f, B, K1f);
        float d2 = fmaf(60.5f, qs, fmaf(-0.5f, B, K2f));
        d[c] = d1 * d2;
    }
    float r = rcpa(d[0] * d[1]);
    acc += __saturatef(n[0] * r * d[1]) + __saturatef(n[1] * r * d[0]);
}

__global__ __launch_bounds__(NT, 2)
void ssim_main_kernel(const float* __restrict__ pred, const float* __restrict__ targ,
                      float* __restrict__ out)
{
    extern __shared__ char sm[];
    float2* rowbuf = (float2*)(sm + OF_ROW);   // 8 buffers of RS2 (u,v) packed
    float*  red    = (float*)(sm + OF_RED);
    __shared__ int s_last;

    const int tid   = threadIdx.x;
    const int bid   = blockIdx.x;
    const int img   = bid / NSTRIP;
    const int strip = bid - img * NSTRIP;
    const int r0    = strip * STRIPH;
    const int r1    = min(HEIGHT, r0 + STRIPH);
    const int yend  = r1 + PADR;
    const int emit0 = r0 + PADR;
    const int start = r0 - PADR;

    const float* __restrict__ P = pred + (size_t)img * (WIDTH * HEIGHT);
    const float* __restrict__ T = targ + (size_t)img * (WIDTH * HEIGHT);
    const int x0 = tid * 2;

    const u64 M1 = pk2(-1.f, -1.f);

    // UV ring in registers (static slots via full unroll below)
    u64 rUV[11][2];
#pragma unroll
    for (int s = 0; s < 11; s++) { rUV[s][0] = 0; rUV[s][1] = 0; }

    // Q ring in smem (per-thread slots, compile-time offsets)
    ulonglong2* qring = (ulonglong2*)(sm + OF_Q) + tid;
    {
        ulonglong2 z2 = make_ulonglong2(0ull, 0ull);
#pragma unroll
        for (int s = 0; s < 11; s++) qring[s * NT] = z2;
    }
    // zero pads of 8 row buffers: idx 3..7 (x=-5..-1) and 520..524 (x=512..516)
    if (tid < 80) {
        int r = tid / 10, k = tid % 10;
        int idx = (k < 5) ? (3 + k) : (520 + (k - 5));
        rowbuf[r * RS2 + idx] = make_float2(0.f, 0.f);
    }

    u64 SUV[2] = {0, 0}, SQ2[2] = {0, 0};
    float acc = 0.f;

    // prefetch rows start..start+3
    float2 pf_p[4] = {}, pf_t[4] = {};
#pragma unroll
    for (int r = 0; r < 4; r++) {
        int y = start + r;
        if (y >= 0 && y < HEIGHT) {
            pf_p[r] = *(const float2*)(P + (size_t)y * WIDTH + x0);
            pf_t[r] = *(const float2*)(T + (size_t)y * WIDTH + x0);
        }
    }

    __syncthreads();   // pads + zeroed ring visible

    int kpar = 0;
    for (int y0 = start; y0 < yend; y0 += 44, kpar ^= 1) {
#pragma unroll
        for (int p = 0; p < 11; p++) {
            const int base = y0 + 4 * p;
            if (base < yend) {                   // uniform across block
                const int setb = (kpar ^ (p & 1)) * 4;
                // write 4 rows (zeros for invalid rows -> branch-free compute)
#pragma unroll
                for (int r = 0; r < 4; r++) {
                    const int y = base + r;
                    float4 w = make_float4(0.f, 0.f, 0.f, 0.f);
                    if (y >= 0 && y < HEIGHT) {
                        w = make_float4(pf_p[r].x + pf_t[r].x, pf_p[r].x - pf_t[r].x,
                                        pf_p[r].y + pf_t[r].y, pf_p[r].y - pf_t[r].y);
                    }
                    *(float4*)(rowbuf + (setb + r) * RS2 + x0 + 8) = w;
                }
                __syncthreads();   // buffer set visible

                // prefetch the next 4 rows (consumed next iteration)
#pragma unroll
                for (int r = 0; r < 4; r++) {
                    const int y = base + 4 + r;
                    if (y >= 0 && y < HEIGHT) {
                        pf_p[r] = *(const float2*)(P + (size_t)y * WIDTH + x0);
                        pf_t[r] = *(const float2*)(T + (size_t)y * WIDTH + x0);
                    }
                }

                // software-pipelined processing: taps+qring for row r+1 are
                // loaded before row r's math (1-row lookahead).
                u64 Tn[12];
                ulonglong2 qn;
                load_taps(rowbuf + (setb + 0) * RS2, x0, Tn);
                qn = qring[((4 * p + 0) % 11) * NT];
#pragma unroll
                for (int r = 0; r < 4; r++) {
                    u64 Tc[12];
#pragma unroll
                    for (int k = 0; k < 12; k++) Tc[k] = Tn[k];
                    ulonglong2 qc = qn;
                    if (r < 3) {
                        load_taps(rowbuf + (setb + r + 1) * RS2, x0, Tn);
                        qn = qring[((4 * p + r + 1) % 11) * NT];
                    }
                    u64 hUV[2], hQ[2];
                    hwin_math(Tc, hUV, hQ);
                    const int sl = (4 * p + r) % 11;
                    SUV[0] = add2(SUV[0], fma2(rUV[sl][0], M1, hUV[0]));
                    SUV[1] = add2(SUV[1], fma2(rUV[sl][1], M1, hUV[1]));
                    SQ2[0] = add2(SQ2[0], fma2(qc.x, M1, hQ[0]));
                    SQ2[1] = add2(SQ2[1], fma2(qc.y, M1, hQ[1]));
                    rUV[sl][0] = hUV[0]; rUV[sl][1] = hUV[1];
                    qring[sl * NT] = make_ulonglong2(hQ[0], hQ[1]);
                    if (base + r >= emit0 && base + r < yend)
                        emit2(SUV, SQ2, acc);
                }
            }
        }
    }

    // deterministic block reduction
    red[tid] = acc;
    __syncthreads();
#pragma unroll
    for (int s = NT / 2; s > 0; s >>= 1) {
        if (tid < s) red[tid] += red[tid + s];
        __syncthreads();
    }
    if (tid == 0) {
        g_partials[bid] = red[0];
        __threadfence();
        unsigned int c = atomicAdd(&g_count, 1);
        s_last = (c == NBLOCKS - 1);
    }
    __syncthreads();
    if (s_last) {
        if (tid < 16) {
            float s = 0.f;
#pragma unroll
            for (int j = 0; j < 3 * NSTRIP; j++)
                s += __ldcg(&g_partials[tid * (3 * NSTRIP) + j]);
            out[tid] = 1.f - s * (1.f / (3.f * 512.f * 512.f));
        }
        if (tid == 0) g_count = 0;   // reset for next graph replay
    }
}

extern "C" void kernel_launch(void* const* d_in, const int* in_sizes, int n_in,
                              void* d_out, int out_size) {
    const float* pred = (const float*)d_in[0];
    const float* targ = (const float*)d_in[1];
    cudaFuncSetAttribute(ssim_main_kernel,
                         cudaFuncAttributeMaxDynamicSharedMemorySize, SMEM_SZ);
    ssim_main_kernel<<<NBLOCKS, NT, SMEM_SZ>>>(pred, targ, (float*)d_out);
}